// round 3
// baseline (speedup 1.0000x reference)
#include <cuda_runtime.h>
#include <cstdint>

// Grid is 128^3
#define GRID_N (128*128*128)   // 2,097,152
#define SCAN_BLOCKS 1024       // 1024 blocks * 256 threads * 8 flags = 2,097,152

__device__ float g_density[GRID_N];
__device__ __align__(8) unsigned char g_active[GRID_N];
__device__ unsigned int g_blocksums[SCAN_BLOCKS];
__device__ unsigned int g_blockoffs[SCAN_BLOCKS];
__device__ unsigned int g_count;
__device__ unsigned int g_cells[GRID_N];

// ---------------------------------------------------------------------------
// Scatter point features into density grid + mark active (3x3x3 neighborhood)
__global__ void scatter_kernel(const int* __restrict__ idx,
                               const float* __restrict__ feat, int n) {
    int i = blockIdx.x * blockDim.x + threadIdx.x;
    if (i >= n) return;
    int x = idx[3*i], y = idx[3*i+1], z = idx[3*i+2];
    unsigned lin = (x << 14) | (y << 7) | z;
    atomicAdd(&g_density[lin], feat[i]);
    #pragma unroll
    for (int di = -1; di <= 1; di++)
        #pragma unroll
        for (int dj = -1; dj <= 1; dj++)
            #pragma unroll
            for (int dk = -1; dk <= 1; dk++) {
                int nx = x + di, ny = y + dj, nz = z + dk;
                if ((unsigned)nx < 128u && (unsigned)ny < 128u && (unsigned)nz < 128u)
                    g_active[(nx << 14) | (ny << 7) | nz] = 1;  // racy stores of 1: fine
            }
}

// ---- prefix scan over 2M flags: 3 kernels -------------------------------
__global__ void scan1_kernel() {
    int base = blockIdx.x * 2048 + threadIdx.x * 8;
    unsigned long long v = *(const unsigned long long*)(g_active + base);
    unsigned s = (unsigned)((v * 0x0101010101010101ULL) >> 56);
    #pragma unroll
    for (int o = 16; o; o >>= 1) s += __shfl_down_sync(0xFFFFFFFFu, s, o);
    __shared__ unsigned ws[8];
    if ((threadIdx.x & 31) == 0) ws[threadIdx.x >> 5] = s;
    __syncthreads();
    if (threadIdx.x == 0) {
        unsigned t = 0;
        #pragma unroll
        for (int i = 0; i < 8; i++) t += ws[i];
        g_blocksums[blockIdx.x] = t;
    }
}

__global__ void scan2_kernel() {
    __shared__ unsigned sh[SCAN_BLOCKS];
    unsigned v = g_blocksums[threadIdx.x];
    sh[threadIdx.x] = v;
    __syncthreads();
    for (int o = 1; o < SCAN_BLOCKS; o <<= 1) {
        unsigned t = (threadIdx.x >= (unsigned)o) ? sh[threadIdx.x - o] : 0u;
        __syncthreads();
        sh[threadIdx.x] += t;
        __syncthreads();
    }
    g_blockoffs[threadIdx.x] = sh[threadIdx.x] - v;  // exclusive
    if (threadIdx.x == SCAN_BLOCKS - 1) g_count = sh[SCAN_BLOCKS - 1];
}

__global__ void scan3_kernel() {
    int base = blockIdx.x * 2048 + threadIdx.x * 8;
    unsigned long long v = *(const unsigned long long*)(g_active + base);
    unsigned s = (unsigned)((v * 0x0101010101010101ULL) >> 56);
    unsigned lane = threadIdx.x & 31, wid = threadIdx.x >> 5;
    unsigned incl = s;
    #pragma unroll
    for (int o = 1; o < 32; o <<= 1) {
        unsigned t = __shfl_up_sync(0xFFFFFFFFu, incl, o);
        if (lane >= (unsigned)o) incl += t;
    }
    unsigned excl = incl - s;
    __shared__ unsigned ws[8];
    if (lane == 31) ws[wid] = incl;
    __syncthreads();
    unsigned woff = 0;
    for (unsigned i = 0; i < wid; i++) woff += ws[i];
    unsigned pos = g_blockoffs[blockIdx.x] + woff + excl;
    #pragma unroll
    for (int i = 0; i < 8; i++) {
        if ((v >> (i * 8)) & 1ULL) g_cells[pos++] = (unsigned)(base + i);
    }
}

// ---- fused output writer: coords + conv features ------------------------
// Packed dual-fp32 FMA (sm_100+): d = a*b+d on 2 lanes per instruction.
__device__ __forceinline__ void fma_x2(unsigned long long& d,
                                       unsigned long long a,
                                       unsigned long long b) {
    asm("fma.rn.f32x2 %0, %1, %2, %0;" : "+l"(d) : "l"(a), "l"(b));
}

// 4 threads cooperate on one output row (16 channels each).
__global__ void __launch_bounds__(256)
feat_kernel(const float* __restrict__ kw,
            float* __restrict__ outc,   // [rows,3] coords (may be null)
            float* __restrict__ outf,   // [rows,64] features (may be null)
            int rows) {
    __shared__ float Ks[27 * 64];
    for (int i = threadIdx.x; i < 27 * 64; i += blockDim.x) Ks[i] = kw[i];
    __syncthreads();

    int gid = blockIdx.x * blockDim.x + threadIdx.x;
    int r = gid >> 2;          // row
    int p = gid & 3;           // channel-quarter [0,4)
    if (r >= rows) return;
    unsigned M = g_count;

    if (r >= (int)M) {
        if (outc && p == 0) {
            outc[3*r + 0] = 128.0f;
            outc[3*r + 1] = 128.0f;
            outc[3*r + 2] = 128.0f;
        }
        if (outf) {
            float4* o = (float4*)(outf + (size_t)r * 64 + p * 16);
            float4 z4 = make_float4(0.f, 0.f, 0.f, 0.f);
            #pragma unroll
            for (int i = 0; i < 4; i++) o[i] = z4;
        }
        return;
    }

    unsigned lin = g_cells[r];
    int x = lin >> 14, y = (lin >> 7) & 127, z = lin & 127;
    if (outc && p == 0) {
        outc[3*r + 0] = (float)x;
        outc[3*r + 1] = (float)y;
        outc[3*r + 2] = (float)z;
    }
    if (!outf) return;

    // Prefetch all 27 neighbor densities (high MLP; ptxas batches the LDGs).
    float d[27];
    #pragma unroll
    for (int t = 0; t < 27; t++) {
        int di = t / 9 - 1, dj = (t / 3) % 3 - 1, dk = t % 3 - 1;
        int nx = x + di, ny = y + dj, nz = z + dk;
        bool ok = (unsigned)nx < 128u && (unsigned)ny < 128u && (unsigned)nz < 128u;
        d[t] = ok ? g_density[(nx << 14) | (ny << 7) | nz] : 0.0f;
    }

    unsigned long long acc[8];  // 16 channels as 8 packed fp32 pairs
    #pragma unroll
    for (int j = 0; j < 8; j++) acc[j] = 0ULL;

    const float* Kp = Ks + p * 16;
    #pragma unroll
    for (int t = 0; t < 27; t++) {
        unsigned du = __float_as_uint(d[t]);
        unsigned long long dd = ((unsigned long long)du << 32) | du;  // (d,d)
        const ulonglong2* K2 = (const ulonglong2*)(Kp + t * 64);      // 16B broadcast loads
        #pragma unroll
        for (int i = 0; i < 4; i++) {
            ulonglong2 kv = K2[i];
            fma_x2(acc[2*i + 0], kv.x, dd);
            fma_x2(acc[2*i + 1], kv.y, dd);
        }
    }

    ulonglong2* o = (ulonglong2*)(outf + (size_t)r * 64 + p * 16);
    #pragma unroll
    for (int i = 0; i < 4; i++) {
        ulonglong2 v; v.x = acc[2*i]; v.y = acc[2*i + 1];
        o[i] = v;
    }
}

// ---------------------------------------------------------------------------
extern "C" void kernel_launch(void* const* d_in, const int* in_sizes, int n_in,
                              void* d_out, int out_size) {
    const int*   indices  = (const int*)d_in[0];    // [N,3] int32
    const float* features = (const float*)d_in[1];  // [N,1] float32
    const float* kw       = (const float*)d_in[2];  // [3,3,3,1,64] float32

    int n = in_sizes[0] / 3;
    int rows = n * 27;
    float* out = (float*)d_out;

    // zero density + active via memset nodes
    void* p_density = nullptr;
    void* p_active  = nullptr;
    cudaGetSymbolAddress(&p_density, g_density);
    cudaGetSymbolAddress(&p_active,  g_active);
    cudaMemsetAsync(p_density, 0, GRID_N * sizeof(float));
    cudaMemsetAsync(p_active,  0, GRID_N);

    scatter_kernel<<<(n + 255) / 256, 256>>>(indices, features, n);
    scan1_kernel<<<SCAN_BLOCKS, 256>>>();
    scan2_kernel<<<1, SCAN_BLOCKS>>>();
    scan3_kernel<<<SCAN_BLOCKS, 256>>>();

    long long tthreads = (long long)rows * 4;
    int rblocks = (int)((tthreads + 255) / 256);
    if (out_size == rows * 64) {
        feat_kernel<<<rblocks, 256>>>(kw, nullptr, out, rows);
    } else if (out_size == rows * 3) {
        feat_kernel<<<rblocks, 256>>>(kw, out, nullptr, rows);
    } else {
        // concatenated [uniq.ravel() | out_feat.ravel()] as float32
        feat_kernel<<<rblocks, 256>>>(kw, out, out + (size_t)rows * 3, rows);
    }
}

// round 4
// speedup vs baseline: 1.4873x; 1.4873x over previous
#include <cuda_runtime.h>
#include <cstdint>

// Grid is 128^3 logical; density is padded to 130^3 (1-voxel zero border).
#define GRID_N (128*128*128)          // 2,097,152
#define PADW   130
#define PGRID_N (PADW*PADW*PADW)      // 2,197,000
#define SCAN_BLOCKS 1024              // 1024 * 256 * 8 = 2,097,152

__device__ float g_pdensity[PGRID_N];
__device__ __align__(8) unsigned char g_active[GRID_N];
__device__ unsigned int g_blocksums[SCAN_BLOCKS];
__device__ unsigned int g_blockoffs[SCAN_BLOCKS];
__device__ unsigned int g_count;
__device__ unsigned int g_cells[GRID_N];

// neighbor offsets in the padded grid: di*16900 + dj*130 + dk, t = (di+1)*9+(dj+1)*3+(dk+1)
// (two trailing zeros so the depth-2 prefetch can read t+2 unconditionally)
__constant__ int c_off[29] = {
    -17031,-17030,-17029,-16901,-16900,-16899,-16771,-16770,-16769,
      -131,  -130,  -129,    -1,     0,     1,   129,   130,   131,
     16769, 16770, 16771, 16899, 16900, 16901, 17029, 17030, 17031,
     0, 0};

// ---------------------------------------------------------------------------
// Scatter features into padded density grid + mark active (3x3x3) flags.
__global__ void scatter_kernel(const int* __restrict__ idx,
                               const float* __restrict__ feat, int n) {
    int i = blockIdx.x * blockDim.x + threadIdx.x;
    if (i >= n) return;
    int x = idx[3*i], y = idx[3*i+1], z = idx[3*i+2];
    int plin = ((x + 1) * PADW + (y + 1)) * PADW + (z + 1);
    atomicAdd(&g_pdensity[plin], feat[i]);
    #pragma unroll
    for (int di = -1; di <= 1; di++)
        #pragma unroll
        for (int dj = -1; dj <= 1; dj++)
            #pragma unroll
            for (int dk = -1; dk <= 1; dk++) {
                int nx = x + di, ny = y + dj, nz = z + dk;
                if ((unsigned)nx < 128u && (unsigned)ny < 128u && (unsigned)nz < 128u)
                    g_active[(nx << 14) | (ny << 7) | nz] = 1;  // racy stores of 1: fine
            }
}

// ---- prefix scan over 2M flags: 3 kernels -------------------------------
__global__ void scan1_kernel() {
    int base = blockIdx.x * 2048 + threadIdx.x * 8;
    unsigned long long v = *(const unsigned long long*)(g_active + base);
    unsigned s = (unsigned)((v * 0x0101010101010101ULL) >> 56);
    #pragma unroll
    for (int o = 16; o; o >>= 1) s += __shfl_down_sync(0xFFFFFFFFu, s, o);
    __shared__ unsigned ws[8];
    if ((threadIdx.x & 31) == 0) ws[threadIdx.x >> 5] = s;
    __syncthreads();
    if (threadIdx.x == 0) {
        unsigned t = 0;
        #pragma unroll
        for (int i = 0; i < 8; i++) t += ws[i];
        g_blocksums[blockIdx.x] = t;
    }
}

__global__ void scan2_kernel() {
    __shared__ unsigned sh[SCAN_BLOCKS];
    unsigned v = g_blocksums[threadIdx.x];
    sh[threadIdx.x] = v;
    __syncthreads();
    for (int o = 1; o < SCAN_BLOCKS; o <<= 1) {
        unsigned t = (threadIdx.x >= (unsigned)o) ? sh[threadIdx.x - o] : 0u;
        __syncthreads();
        sh[threadIdx.x] += t;
        __syncthreads();
    }
    g_blockoffs[threadIdx.x] = sh[threadIdx.x] - v;  // exclusive
    if (threadIdx.x == SCAN_BLOCKS - 1) g_count = sh[SCAN_BLOCKS - 1];
}

__global__ void scan3_kernel() {
    int base = blockIdx.x * 2048 + threadIdx.x * 8;
    unsigned long long v = *(const unsigned long long*)(g_active + base);
    unsigned s = (unsigned)((v * 0x0101010101010101ULL) >> 56);
    unsigned lane = threadIdx.x & 31, wid = threadIdx.x >> 5;
    unsigned incl = s;
    #pragma unroll
    for (int o = 1; o < 32; o <<= 1) {
        unsigned t = __shfl_up_sync(0xFFFFFFFFu, incl, o);
        if (lane >= (unsigned)o) incl += t;
    }
    unsigned excl = incl - s;
    __shared__ unsigned ws[8];
    if (lane == 31) ws[wid] = incl;
    __syncthreads();
    unsigned woff = 0;
    for (unsigned i = 0; i < wid; i++) woff += ws[i];
    unsigned pos = g_blockoffs[blockIdx.x] + woff + excl;
    #pragma unroll
    for (int i = 0; i < 8; i++) {
        if ((v >> (i * 8)) & 1ULL) g_cells[pos++] = (unsigned)(base + i);
    }
}

// ---- fused output writer: coords + conv features ------------------------
// Packed dual-fp32 FMA (sm_100+): d = a*b+d on 2 lanes per instruction.
__device__ __forceinline__ void fma_x2(unsigned long long& d,
                                       unsigned long long a,
                                       unsigned long long b) {
    asm("fma.rn.f32x2 %0, %1, %2, %0;" : "+l"(d) : "l"(a), "l"(b));
}

// 2 threads cooperate on one output row (32 channels each).
__global__ void __launch_bounds__(256)
feat_kernel(const float* __restrict__ kw,
            float* __restrict__ outc,   // [rows,3] coords (may be null)
            float* __restrict__ outf,   // [rows,64] features (may be null)
            int rows) {
    __shared__ float Ks[27 * 64];
    for (int i = threadIdx.x; i < 27 * 64; i += blockDim.x) Ks[i] = kw[i];
    __syncthreads();

    int gid = blockIdx.x * blockDim.x + threadIdx.x;
    int r = gid >> 1;          // row
    int p = gid & 1;           // channel half
    if (r >= rows) return;
    unsigned M = g_count;

    if (r >= (int)M) {
        if (outc && p == 0) {
            outc[3*r + 0] = 128.0f;
            outc[3*r + 1] = 128.0f;
            outc[3*r + 2] = 128.0f;
        }
        if (outf) {
            float4* o = (float4*)(outf + (size_t)r * 64 + p * 32);
            float4 z4 = make_float4(0.f, 0.f, 0.f, 0.f);
            #pragma unroll
            for (int i = 0; i < 8; i++) o[i] = z4;
        }
        return;
    }

    unsigned lin = g_cells[r];
    int x = lin >> 14, y = (lin >> 7) & 127, z = lin & 127;
    if (outc && p == 0) {
        outc[3*r + 0] = (float)x;
        outc[3*r + 1] = (float)y;
        outc[3*r + 2] = (float)z;
    }
    if (!outf) return;

    int base = ((x + 1) * PADW + (y + 1)) * PADW + (z + 1);

    unsigned long long acc[16];  // 32 channels as 16 packed fp32 pairs
    #pragma unroll
    for (int j = 0; j < 16; j++) acc[j] = 0ULL;

    const float* Kp = Ks + p * 32;

    // Depth-2 software pipeline over the 27 taps: load t+2 while FMA-ing t.
    float d0 = g_pdensity[base + c_off[0]];
    float d1 = g_pdensity[base + c_off[1]];
    #pragma unroll 1
    for (int t = 0; t < 27; t++) {
        float d2 = g_pdensity[base + c_off[t + 2]];  // [27],[28] are 0-offsets: harmless
        unsigned du = __float_as_uint(d0);
        unsigned long long dd = ((unsigned long long)du << 32) | du;  // (d,d)
        const ulonglong2* K2 = (const ulonglong2*)(Kp + t * 64);
        #pragma unroll
        for (int i = 0; i < 8; i++) {
            ulonglong2 kv = K2[i];
            fma_x2(acc[2*i + 0], kv.x, dd);
            fma_x2(acc[2*i + 1], kv.y, dd);
        }
        d0 = d1; d1 = d2;
    }

    ulonglong2* o = (ulonglong2*)(outf + (size_t)r * 64 + p * 32);
    #pragma unroll
    for (int i = 0; i < 8; i++) {
        ulonglong2 v; v.x = acc[2*i]; v.y = acc[2*i + 1];
        o[i] = v;
    }
}

// ---------------------------------------------------------------------------
extern "C" void kernel_launch(void* const* d_in, const int* in_sizes, int n_in,
                              void* d_out, int out_size) {
    const int*   indices  = (const int*)d_in[0];    // [N,3] int32
    const float* features = (const float*)d_in[1];  // [N,1] float32
    const float* kw       = (const float*)d_in[2];  // [3,3,3,1,64] float32

    int n = in_sizes[0] / 3;
    int rows = n * 27;
    float* out = (float*)d_out;

    // zero density + active via memset nodes
    void* p_density = nullptr;
    void* p_active  = nullptr;
    cudaGetSymbolAddress(&p_density, g_pdensity);
    cudaGetSymbolAddress(&p_active,  g_active);
    cudaMemsetAsync(p_density, 0, PGRID_N * sizeof(float));
    cudaMemsetAsync(p_active,  0, GRID_N);

    scatter_kernel<<<(n + 255) / 256, 256>>>(indices, features, n);
    scan1_kernel<<<SCAN_BLOCKS, 256>>>();
    scan2_kernel<<<1, SCAN_BLOCKS>>>();
    scan3_kernel<<<SCAN_BLOCKS, 256>>>();

    long long tthreads = (long long)rows * 2;
    int rblocks = (int)((tthreads + 255) / 256);
    if (out_size == rows * 64) {
        feat_kernel<<<rblocks, 256>>>(kw, nullptr, out, rows);
    } else if (out_size == rows * 3) {
        feat_kernel<<<rblocks, 256>>>(kw, out, nullptr, rows);
    } else {
        // concatenated [uniq.ravel() | out_feat.ravel()] as float32
        feat_kernel<<<rblocks, 256>>>(kw, out, out + (size_t)rows * 3, rows);
    }
}

// round 5
// speedup vs baseline: 1.9110x; 1.2849x over previous
#include <cuda_runtime.h>
#include <cstdint>

// Grid is 128^3 logical; density is padded to 130^3 (1-voxel zero border).
#define GRID_N (128*128*128)          // 2,097,152
#define PADW   130
#define PGRID_N (PADW*PADW*PADW)      // 2,197,000
#define SCAN_BLOCKS 1024              // 1024 * 256 * 8 = 2,097,152

__device__ float g_pdensity[PGRID_N];
__device__ __align__(8) unsigned char g_active[GRID_N];
__device__ unsigned int g_blocksums[SCAN_BLOCKS];
__device__ unsigned int g_blockoffs[SCAN_BLOCKS];
__device__ unsigned int g_count;
__device__ unsigned int g_cells[GRID_N];

// neighbor offsets in padded grid: di*16900 + dj*130 + dk, t=(di+1)*9+(dj+1)*3+(dk+1)
// (three trailing zeros so depth-3 prefetch can read t+3 unconditionally)
__constant__ int c_off[30] = {
    -17031,-17030,-17029,-16901,-16900,-16899,-16771,-16770,-16769,
      -131,  -130,  -129,    -1,     0,     1,   129,   130,   131,
     16769, 16770, 16771, 16899, 16900, 16901, 17029, 17030, 17031,
     0, 0, 0};

// ---------------------------------------------------------------------------
// Scatter features into padded density grid + mark active (3x3x3) flags.
__global__ void scatter_kernel(const int* __restrict__ idx,
                               const float* __restrict__ feat, int n) {
    int i = blockIdx.x * blockDim.x + threadIdx.x;
    if (i >= n) return;
    int x = idx[3*i], y = idx[3*i+1], z = idx[3*i+2];
    int plin = ((x + 1) * PADW + (y + 1)) * PADW + (z + 1);
    atomicAdd(&g_pdensity[plin], feat[i]);
    #pragma unroll
    for (int di = -1; di <= 1; di++)
        #pragma unroll
        for (int dj = -1; dj <= 1; dj++)
            #pragma unroll
            for (int dk = -1; dk <= 1; dk++) {
                int nx = x + di, ny = y + dj, nz = z + dk;
                if ((unsigned)nx < 128u && (unsigned)ny < 128u && (unsigned)nz < 128u)
                    g_active[(nx << 14) | (ny << 7) | nz] = 1;  // racy stores of 1: fine
            }
}

// ---- prefix scan over 2M flags: 3 kernels -------------------------------
__global__ void scan1_kernel() {
    int base = blockIdx.x * 2048 + threadIdx.x * 8;
    unsigned long long v = *(const unsigned long long*)(g_active + base);
    unsigned s = (unsigned)((v * 0x0101010101010101ULL) >> 56);
    #pragma unroll
    for (int o = 16; o; o >>= 1) s += __shfl_down_sync(0xFFFFFFFFu, s, o);
    __shared__ unsigned ws[8];
    if ((threadIdx.x & 31) == 0) ws[threadIdx.x >> 5] = s;
    __syncthreads();
    if (threadIdx.x == 0) {
        unsigned t = 0;
        #pragma unroll
        for (int i = 0; i < 8; i++) t += ws[i];
        g_blocksums[blockIdx.x] = t;
    }
}

__global__ void scan2_kernel() {
    __shared__ unsigned sh[SCAN_BLOCKS];
    unsigned v = g_blocksums[threadIdx.x];
    sh[threadIdx.x] = v;
    __syncthreads();
    for (int o = 1; o < SCAN_BLOCKS; o <<= 1) {
        unsigned t = (threadIdx.x >= (unsigned)o) ? sh[threadIdx.x - o] : 0u;
        __syncthreads();
        sh[threadIdx.x] += t;
        __syncthreads();
    }
    g_blockoffs[threadIdx.x] = sh[threadIdx.x] - v;  // exclusive
    if (threadIdx.x == SCAN_BLOCKS - 1) g_count = sh[SCAN_BLOCKS - 1];
}

__global__ void scan3_kernel() {
    int base = blockIdx.x * 2048 + threadIdx.x * 8;
    unsigned long long v = *(const unsigned long long*)(g_active + base);
    unsigned s = (unsigned)((v * 0x0101010101010101ULL) >> 56);
    unsigned lane = threadIdx.x & 31, wid = threadIdx.x >> 5;
    unsigned incl = s;
    #pragma unroll
    for (int o = 1; o < 32; o <<= 1) {
        unsigned t = __shfl_up_sync(0xFFFFFFFFu, incl, o);
        if (lane >= (unsigned)o) incl += t;
    }
    unsigned excl = incl - s;
    __shared__ unsigned ws[8];
    if (lane == 31) ws[wid] = incl;
    __syncthreads();
    unsigned woff = 0;
    for (unsigned i = 0; i < wid; i++) woff += ws[i];
    unsigned pos = g_blockoffs[blockIdx.x] + woff + excl;
    #pragma unroll
    for (int i = 0; i < 8; i++) {
        if ((v >> (i * 8)) & 1ULL) g_cells[pos++] = (unsigned)(base + i);
    }
}

// ---- fused output writer: coords + conv features ------------------------
// Packed dual-fp32 FMA (sm_100+): d = a*b+d on 2 lanes per instruction.
__device__ __forceinline__ void fma_x2(unsigned long long& d,
                                       unsigned long long a,
                                       unsigned long long b) {
    asm("fma.rn.f32x2 %0, %1, %2, %0;" : "+l"(d) : "l"(a), "l"(b));
}

// One thread per output row: 64 channels, depth-3 pipelined tap loop.
__global__ void __launch_bounds__(256)
feat_kernel(const float* __restrict__ kw,
            float* __restrict__ outc,   // [rows,3] coords (may be null)
            float* __restrict__ outf,   // [rows,64] features (may be null)
            int rows) {
    __shared__ float Ks[27 * 64];
    for (int i = threadIdx.x; i < 27 * 64; i += blockDim.x) Ks[i] = kw[i];
    __syncthreads();

    int r = blockIdx.x * blockDim.x + threadIdx.x;
    if (r >= rows) return;
    unsigned M = g_count;

    if (r >= (int)M) {
        if (outc) {
            outc[3*r + 0] = 128.0f;
            outc[3*r + 1] = 128.0f;
            outc[3*r + 2] = 128.0f;
        }
        if (outf) {
            float4* o = (float4*)(outf + (size_t)r * 64);
            float4 z4 = make_float4(0.f, 0.f, 0.f, 0.f);
            #pragma unroll
            for (int i = 0; i < 16; i++) o[i] = z4;
        }
        return;
    }

    unsigned lin = g_cells[r];
    int x = lin >> 14, y = (lin >> 7) & 127, z = lin & 127;
    if (outc) {
        outc[3*r + 0] = (float)x;
        outc[3*r + 1] = (float)y;
        outc[3*r + 2] = (float)z;
    }
    if (!outf) return;

    int base = ((x + 1) * PADW + (y + 1)) * PADW + (z + 1);

    unsigned long long acc[32];  // 64 channels as 32 packed fp32 pairs
    #pragma unroll
    for (int j = 0; j < 32; j++) acc[j] = 0ULL;

    // Depth-3 rotating prefetch: keeps ~3 loads in flight (low MLP_p1, no
    // L1tex queue pileup), hides L2 latency behind ~130cyc of FMA/LDS issue.
    float d0 = g_pdensity[base + c_off[0]];
    float d1 = g_pdensity[base + c_off[1]];
    float d2 = g_pdensity[base + c_off[2]];
    #pragma unroll 1
    for (int t = 0; t < 27; t++) {
        float dn = g_pdensity[base + c_off[t + 3]];  // trailing zeros: harmless
        unsigned du = __float_as_uint(d0);
        unsigned long long dd = ((unsigned long long)du << 32) | du;  // (d,d)
        const ulonglong2* K2 = (const ulonglong2*)(Ks + t * 64);
        #pragma unroll
        for (int i = 0; i < 16; i++) {
            ulonglong2 kv = K2[i];               // broadcast LDS.128
            fma_x2(acc[2*i + 0], kv.x, dd);
            fma_x2(acc[2*i + 1], kv.y, dd);
        }
        d0 = d1; d1 = d2; d2 = dn;
    }

    ulonglong2* o = (ulonglong2*)(outf + (size_t)r * 64);
    #pragma unroll
    for (int i = 0; i < 16; i++) {
        ulonglong2 v; v.x = acc[2*i]; v.y = acc[2*i + 1];
        o[i] = v;
    }
}

// ---------------------------------------------------------------------------
extern "C" void kernel_launch(void* const* d_in, const int* in_sizes, int n_in,
                              void* d_out, int out_size) {
    const int*   indices  = (const int*)d_in[0];    // [N,3] int32
    const float* features = (const float*)d_in[1];  // [N,1] float32
    const float* kw       = (const float*)d_in[2];  // [3,3,3,1,64] float32

    int n = in_sizes[0] / 3;
    int rows = n * 27;
    float* out = (float*)d_out;

    // zero density + active via memset nodes
    void* p_density = nullptr;
    void* p_active  = nullptr;
    cudaGetSymbolAddress(&p_density, g_pdensity);
    cudaGetSymbolAddress(&p_active,  g_active);
    cudaMemsetAsync(p_density, 0, PGRID_N * sizeof(float));
    cudaMemsetAsync(p_active,  0, GRID_N);

    scatter_kernel<<<(n + 255) / 256, 256>>>(indices, features, n);
    scan1_kernel<<<SCAN_BLOCKS, 256>>>();
    scan2_kernel<<<1, SCAN_BLOCKS>>>();
    scan3_kernel<<<SCAN_BLOCKS, 256>>>();

    int rblocks = (rows + 255) / 256;
    if (out_size == rows * 64) {
        feat_kernel<<<rblocks, 256>>>(kw, nullptr, out, rows);
    } else if (out_size == rows * 3) {
        feat_kernel<<<rblocks, 256>>>(kw, out, nullptr, rows);
    } else {
        // concatenated [uniq.ravel() | out_feat.ravel()] as float32
        feat_kernel<<<rblocks, 256>>>(kw, out, out + (size_t)rows * 3, rows);
    }
}